// round 5
// baseline (speedup 1.0000x reference)
#include <cuda_runtime.h>
#include <stdint.h>
#include <math.h>

// ============================================================================
// ContrastiveAlignmentLoss — JAX-semantics replication on GB300 (sm_103a).
// jax_threefry_partitionable=True semantics:
//   random_bits(key,32): elem p -> TF(key,(0,p)), bits = o0^o1
//   split(key,2): key_i = TF(key,(0,i))
// Selection semantics frozen since R2 (deterministic rel_err 6.85e-4):
// the candidate multiset {j: lab[j]!=cls && bits>=TBITS} and the
// (value, lowest-index-tie) top-256 rule are unchanged; this revision only
// restructures WHERE the label filter happens (post-sweep) and fuses the
// permutation into one single-block kernel.
// ============================================================================

#define NPTS   20000
#define SANCH  5000
#define NNEG   256
#define TPRE   8126464u      // 2^23 - 2^18
#define TBITS  0xF8000000u   // TPRE << 9
#define CANDMAX 1024
#define NBIN   2048
#define NBLK   888           // 148 SM * 6 CTA
#define INV_TEMP (1.0f/0.07f)

typedef unsigned long long u64;

static __device__ uint32_t g_keys[6];    // kneg, sub1, sub2
static __device__ u64      g_packed[NPTS];
static __device__ u64      g_tmp[NPTS];
static __device__ int      g_val1[NPTS];
static __device__ int      g_val2[SANCH];
static __device__ double   g_loss;

// ---------------- Threefry-2x32, 20 rounds (JAX/Random123) -----------------
__device__ __forceinline__ void tf2x32(uint32_t k0, uint32_t k1,
                                       uint32_t c0, uint32_t c1,
                                       uint32_t& o0, uint32_t& o1) {
    uint32_t ks2 = k0 ^ k1 ^ 0x1BD11BDAu;
    uint32_t x0 = c0 + k0;
    uint32_t x1 = c1 + k1;
#define TF_R(r) { x0 += x1; x1 = __funnelshift_l(x1, x1, (r)); x1 ^= x0; }
    TF_R(13) TF_R(15) TF_R(26) TF_R(6)
    x0 += k1;  x1 += ks2 + 1u;
    TF_R(17) TF_R(29) TF_R(16) TF_R(24)
    x0 += ks2; x1 += k0 + 2u;
    TF_R(13) TF_R(15) TF_R(26) TF_R(6)
    x0 += k0;  x1 += k1 + 3u;
    TF_R(17) TF_R(29) TF_R(16) TF_R(24)
    x0 += k1;  x1 += ks2 + 4u;
    TF_R(13) TF_R(15) TF_R(26) TF_R(6)
    x0 += ks2; x1 += k0 + 5u;
#undef TF_R
    o0 = x0; o1 = x1;
}

// ---------------- setup: derive keys, reset accumulator ----------------------
__global__ void k_setup() {
    if (threadIdx.x == 0) {
        uint32_t kp0, kp1, kn0, kn1, r1k0, r1k1, s10, s11, s20, s21;
        tf2x32(0u, 1u, 0u, 0u, kp0, kp1);      // kperm
        tf2x32(0u, 1u, 0u, 1u, kn0, kn1);      // kneg
        tf2x32(kp0, kp1, 0u, 0u, r1k0, r1k1);  // key after round-1 split
        tf2x32(kp0, kp1, 0u, 1u, s10, s11);    // sub1
        tf2x32(r1k0, r1k1, 0u, 1u, s20, s21);  // sub2
        g_keys[0] = kn0; g_keys[1] = kn1;
        g_keys[2] = s10; g_keys[3] = s11;
        g_keys[4] = s20; g_keys[5] = s21;
        g_loss = 0.0;
    }
}

// ---------------- fused permutation: 2 stable bucket sorts, one block -------
__global__ __launch_bounds__(1024, 1)
void k_perm() {
    __shared__ int hist[NBIN];
    __shared__ int base[NBIN];
    __shared__ int cur[NBIN];
    __shared__ u64 wbuf[32][64];
    __shared__ int wtot[32];

    const int tid = threadIdx.x;
    const int lane = tid & 31;
    const int wd   = tid >> 5;

    for (int round = 1; round <= 2; round++) {
        const int kb = (round == 1) ? 2 : 4;
        for (int i = tid; i < NBIN; i += 1024) hist[i] = 0;
        __syncthreads();

        const uint32_t kk0 = g_keys[kb], kk1 = g_keys[kb + 1];
        for (int p = tid; p < NPTS; p += 1024) {
            uint32_t o0, o1;
            tf2x32(kk0, kk1, 0u, (uint32_t)p, o0, o1);
            uint32_t key = o0 ^ o1;
            g_packed[p] = (((u64)key) << 32) | (unsigned)p;   // unique => stable
            atomicAdd(&hist[key >> 21], 1);
        }
        __syncthreads();

        // exclusive scan of 2048 bins: 2 bins/thread + warp scan + warp totals
        int h0 = hist[2 * tid], h1 = hist[2 * tid + 1];
        int tsum = h0 + h1;
        int v = tsum;
#pragma unroll
        for (int off = 1; off < 32; off <<= 1) {
            int n = __shfl_up_sync(0xffffffffu, v, off);
            if (lane >= off) v += n;
        }
        if (lane == 31) wtot[wd] = v;
        __syncthreads();
        int wpre = 0;
        for (int w = 0; w < wd; w++) wpre += wtot[w];
        int excl = wpre + v - tsum;
        base[2 * tid] = excl;          cur[2 * tid] = excl;
        base[2 * tid + 1] = excl + h0; cur[2 * tid + 1] = excl + h0;
        __syncthreads();

        // scatter into buckets
        for (int p = tid; p < NPTS; p += 1024) {
            u64 pk = g_packed[p];
            int bin = (int)(pk >> 53);
            int pos = atomicAdd(&cur[bin], 1);
            g_tmp[pos] = pk;
        }
        __syncthreads();

        // per-bucket exact rank (warp per bucket, smem-buffered)
        for (int w = wd; w < NBIN; w += 32) {
            int start = base[w], m = hist[w];
            if (m == 0) continue;
            if (round == 2 && start >= SANCH) continue;
            if (m <= 64) {
                for (int e = lane; e < m; e += 32) wbuf[wd][e] = g_tmp[start + e];
                __syncwarp();
                for (int e = lane; e < m; e += 32) {
                    u64 me = wbuf[wd][e];
                    int r = 0;
                    for (int f = 0; f < m; f++) r += (wbuf[wd][f] < me) ? 1 : 0;
                    int idx = (int)(me & 0xffffffffu);
                    int slot = start + r;
                    if (round == 1) g_val1[slot] = idx;
                    else if (slot < SANCH) g_val2[slot] = g_val1[idx];
                }
                __syncwarp();
            } else {   // pathological bucket (prob ~0): direct global path
                for (int e = lane; e < m; e += 32) {
                    u64 me = g_tmp[start + e];
                    int r = 0;
                    for (int f = 0; f < m; f++) r += (g_tmp[start + f] < me) ? 1 : 0;
                    int idx = (int)(me & 0xffffffffu);
                    int slot = start + r;
                    if (round == 1) g_val1[slot] = idx;
                    else if (slot < SANCH) g_val2[slot] = g_val1[idx];
                }
            }
        }
        __syncthreads();
    }
}

// ---------------- main: sweep + filter + exact top-256 + InfoNCE ------------
__global__ __launch_bounds__(256, 6)
void k_main(const float* __restrict__ zv, const float* __restrict__ zimg,
            const long long* __restrict__ lab) {
    __shared__ u64 cands[CANDMAX];     // (v - TPRE)<<32 | j  (unfiltered)
    __shared__ u64 cands2[CANDMAX];    // label-filtered
    __shared__ int hist[256];
    __shared__ int sel[NNEG];
    __shared__ u64 eqb[64];
    __shared__ int s_cnt, s_cnt2, s_cgt, s_eq, s_b1, s_nd;
    __shared__ float zrow[64];
    __shared__ float red[8];
    __shared__ float s_m, s_pos;

    const int tid = threadIdx.x;
    const int lane = tid & 31;
    const uint32_t k0 = g_keys[0], k1 = g_keys[1];

    for (int s = blockIdx.x; s < SANCH; s += NBLK) {
        if (tid == 0) { s_cnt = 0; s_cnt2 = 0; s_cgt = 0; s_eq = 0; }
        sel[tid] = 0;
        hist[tid] = 0;
        __syncthreads();

        // ---- sweep: 20000 threefry, prefilter bits >= TBITS (label-free) ----
        const uint32_t base = (uint32_t)s * 20000u;
        for (int j = tid; j < NPTS; j += 256) {
            uint32_t o0, o1;
            tf2x32(k0, k1, 0u, base + (uint32_t)j, o0, o1);
            uint32_t bits = o0 ^ o1;
            if (bits >= TBITS) {                 // == (bits>>9) >= TPRE
                uint32_t v = bits >> 9;
                int q = atomicAdd(&s_cnt, 1);
                if (q < CANDMAX)
                    cands[q] = (((u64)(v - TPRE)) << 32) | (unsigned)j;
            }
        }

        // ---- anchor: idx, class, pos logit, zv row --------------------------
        const int idx = g_val2[s];               // uniform broadcast load
        const int cls = (int)lab[idx];
        if (tid < 32) {
            float a0 = zv[(size_t)idx * 64 + tid], a1 = zv[(size_t)idx * 64 + tid + 32];
            float b0 = zimg[(size_t)idx * 64 + tid], b1 = zimg[(size_t)idx * 64 + tid + 32];
            float ps = a0 * b0 + a1 * b1;
#pragma unroll
            for (int off = 16; off; off >>= 1) ps += __shfl_xor_sync(0xffffffffu, ps, off);
            if (tid == 0) s_pos = ps * INV_TEMP;
        }
        if (tid < 64) zrow[tid] = zv[(size_t)idx * 64 + tid];
        __syncthreads();

        // ---- label filter: identical multiset to the masked sweep -----------
        int cnt = s_cnt; if (cnt > CANDMAX) cnt = CANDMAX;
        for (int t = tid; t < cnt; t += 256) {
            u64 cd = cands[t];
            int j = (int)(cd & 0xffffffffu);
            if ((int)lab[j] != cls) {
                int q = atomicAdd(&s_cnt2, 1);
                cands2[q] = cd;
            }
        }
        __syncthreads();
        int cnt2 = s_cnt2;

        // ---- level-1 histogram on top 8 of the 18 prefiltered bits ----------
        for (int t = tid; t < cnt2; t += 256) {
            uint32_t u = (uint32_t)(cands2[t] >> 32);
            atomicAdd(&hist[u >> 10], 1);
        }
        __syncthreads();
        if (tid == 0) {
            int need = NNEG, b;
            for (b = 255; b > 0; b--) { int h = hist[b]; if (h >= need) break; need -= h; }
            s_b1 = b; s_nd = need;
        }
        __syncthreads();
        const int b1 = s_b1;

        for (int t = tid; t < cnt2; t += 256) {
            u64 cd = cands2[t];
            int bin = (int)((uint32_t)(cd >> 32) >> 10);
            if (bin > b1) {
                int q = atomicAdd(&s_cgt, 1);
                if (q < NNEG) sel[q] = (int)(cd & 0xffffffffu);
            } else if (bin == b1) {
                int q = atomicAdd(&s_eq, 1);
                if (q < 64) eqb[q] = cd;
            }
        }
        __syncthreads();
        if (tid == 0) {
            // take nd best from boundary bin: max value first, ties -> lowest j
            int cg = s_cgt, nd = s_nd, ec = s_eq; if (ec > 64) ec = 64;
            for (int r = 0; r < nd && cg < NNEG; r++) {
                int bi = -1; uint32_t bu = 0; uint32_t bj = 0xffffffffu;
                for (int t = 0; t < ec; t++) {
                    uint32_t u = (uint32_t)(eqb[t] >> 32);
                    uint32_t j = (uint32_t)(eqb[t] & 0xffffffffu);
                    if (j == 0x00ffffffu) continue;
                    if (u > bu || (u == bu && j < bj)) { bu = u; bj = j; bi = t; }
                }
                if (bi < 0) break;
                sel[cg++] = (int)bj;
                eqb[bi] = 0x00ffffffull;
            }
        }
        __syncthreads();

        // ---- similarities for the 256 selected negatives ---------------------
        float x;
        {
            int j = sel[tid];
            const float4* zi4 = (const float4*)(zimg + (size_t)j * 64);
            const float4* zr4 = (const float4*)zrow;
            float acc = 0.f;
#pragma unroll
            for (int q = 0; q < 16; q++) {
                float4 a = zi4[q]; float4 b = zr4[q];
                acc += a.x * b.x + a.y * b.y + a.z * b.z + a.w * b.w;
            }
            x = acc * INV_TEMP;
        }
        const float pos = s_pos;

        float m = x;
#pragma unroll
        for (int off = 16; off; off >>= 1) m = fmaxf(m, __shfl_xor_sync(0xffffffffu, m, off));
        if (lane == 0) red[tid >> 5] = m;
        __syncthreads();
        if (tid == 0) {
            float mm = pos;
#pragma unroll
            for (int w = 0; w < 8; w++) mm = fmaxf(mm, red[w]);
            s_m = mm;
        }
        __syncthreads();
        m = s_m;

        float e = expf(x - m);
#pragma unroll
        for (int off = 16; off; off >>= 1) e += __shfl_xor_sync(0xffffffffu, e, off);
        if (lane == 0) red[tid >> 5] = e;
        __syncthreads();
        if (tid == 0) {
            float ssum = expf(pos - m);
#pragma unroll
            for (int w = 0; w < 8; w++) ssum += red[w];
            atomicAdd(&g_loss, (double)(logf(ssum) + m - pos));
        }
        __syncthreads();   // smem reuse guard for next anchor
    }
}

__global__ void k_final(float* out) {
    out[0] = (float)(0.1 * g_loss / 5000.0);
}

// ---------------- launch ----------------------------------------------------
extern "C" void kernel_launch(void* const* d_in, const int* in_sizes, int n_in,
                              void* d_out, int out_size) {
    const float*     zv  = (const float*)d_in[0];
    const float*     zi  = (const float*)d_in[1];
    const long long* lab = (const long long*)d_in[2];

    k_setup<<<1, 32>>>();
    k_perm<<<1, 1024>>>();
    k_main<<<NBLK, 256>>>(zv, zi, lab);
    k_final<<<1, 1>>>((float*)d_out);
}

// round 6
// speedup vs baseline: 1.5031x; 1.5031x over previous
#include <cuda_runtime.h>
#include <stdint.h>
#include <math.h>

// ============================================================================
// ContrastiveAlignmentLoss — JAX-semantics replication on GB300 (sm_103a).
// jax_threefry_partitionable=True semantics:
//   random_bits(key,32): elem p -> TF(key,(0,p)), bits = o0^o1
//   split(key,2): key_i = TF(key,(0,i))
// R6 = R4 structure (measured 356us) + ONE delta: label-free sweep with
// post-sweep label filter (candidate multiset provably unchanged).
// ============================================================================

#define NPTS   20000
#define SANCH  5000
#define NNEG   256
#define TPRE   8126464u      // 2^23 - 2^18
#define TBITS  0xF8000000u   // TPRE << 9
#define CANDMAX 1024
#define NBIN   2048
#define INV_TEMP (1.0f/0.07f)

typedef unsigned long long u64;

static __device__ uint32_t g_keys[6];    // kneg, sub1, sub2
static __device__ u64      g_packed[NPTS];
static __device__ u64      g_tmp[NPTS];
static __device__ int      g_hist[NBIN];
static __device__ int      g_base[NBIN + 1];
static __device__ int      g_cursor[NBIN];
static __device__ int      g_val1[NPTS];
static __device__ int      g_labS[SANCH];
static __device__ float    g_pos[SANCH];
static __device__ float    g_zvS[SANCH * 64];
static __device__ double   g_loss;

// ---------------- Threefry-2x32, 20 rounds (JAX/Random123) -----------------
__device__ __forceinline__ void tf2x32(uint32_t k0, uint32_t k1,
                                       uint32_t c0, uint32_t c1,
                                       uint32_t& o0, uint32_t& o1) {
    uint32_t ks2 = k0 ^ k1 ^ 0x1BD11BDAu;
    uint32_t x0 = c0 + k0;
    uint32_t x1 = c1 + k1;
#define TF_R(r) { x0 += x1; x1 = __funnelshift_l(x1, x1, (r)); x1 ^= x0; }
    TF_R(13) TF_R(15) TF_R(26) TF_R(6)
    x0 += k1;  x1 += ks2 + 1u;
    TF_R(17) TF_R(29) TF_R(16) TF_R(24)
    x0 += ks2; x1 += k0 + 2u;
    TF_R(13) TF_R(15) TF_R(26) TF_R(6)
    x0 += k0;  x1 += k1 + 3u;
    TF_R(17) TF_R(29) TF_R(16) TF_R(24)
    x0 += k1;  x1 += ks2 + 4u;
    TF_R(13) TF_R(15) TF_R(26) TF_R(6)
    x0 += ks2; x1 += k0 + 5u;
#undef TF_R
    o0 = x0; o1 = x1;
}

// ---------------- setup: keys, hist zero -------------------------------------
__global__ void k_setup() {
    int t = blockIdx.x * blockDim.x + threadIdx.x;
    if (t < NBIN) g_hist[t] = 0;
    if (t == 0) {
        uint32_t kp0, kp1, kn0, kn1, r1k0, r1k1, s10, s11, s20, s21;
        tf2x32(0u, 1u, 0u, 0u, kp0, kp1);      // kperm
        tf2x32(0u, 1u, 0u, 1u, kn0, kn1);      // kneg
        tf2x32(kp0, kp1, 0u, 0u, r1k0, r1k1);  // key after round-1 split
        tf2x32(kp0, kp1, 0u, 1u, s10, s11);    // sub1
        tf2x32(r1k0, r1k1, 0u, 1u, s20, s21);  // sub2
        g_keys[0] = kn0; g_keys[1] = kn1;
        g_keys[2] = s10; g_keys[3] = s11;
        g_keys[4] = s20; g_keys[5] = s21;
        g_loss = 0.0;
    }
}

// ---------------- distribution sort: hash + histogram -----------------------
__global__ void k_hash_hist(int kb) {
    __shared__ int h[NBIN];
    for (int i = threadIdx.x; i < NBIN; i += 256) h[i] = 0;
    __syncthreads();
    int p = blockIdx.x * 256 + threadIdx.x;
    if (p < NPTS) {
        uint32_t o0, o1;
        tf2x32(g_keys[kb], g_keys[kb + 1], 0u, (uint32_t)p, o0, o1);
        uint32_t key = o0 ^ o1;
        g_packed[p] = (((u64)key) << 32) | (unsigned)p;  // unique => stable
        atomicAdd(&h[key >> 21], 1);
    }
    __syncthreads();
    for (int i = threadIdx.x; i < NBIN; i += 256)
        if (h[i]) atomicAdd(&g_hist[i], h[i]);
}

// ---------------- exclusive scan of 2048 bins (1 block) ---------------------
__global__ void k_scan() {
    __shared__ int s[1024];
    int t = threadIdx.x;
    int a = g_hist[2 * t], b = g_hist[2 * t + 1];
    int sum = a + b;
    s[t] = sum; __syncthreads();
#pragma unroll
    for (int off = 1; off < 1024; off <<= 1) {
        int v = (t >= off) ? s[t - off] : 0;
        __syncthreads();
        s[t] += v;
        __syncthreads();
    }
    int excl = s[t] - sum;
    g_base[2 * t]     = excl;
    g_base[2 * t + 1] = excl + a;
    if (t == 1023) g_base[NBIN] = s[t];
    g_cursor[2 * t] = 0; g_cursor[2 * t + 1] = 0;
}

// ---------------- scatter into buckets ---------------------------------------
__global__ void k_scatter() {
    int p = blockIdx.x * 256 + threadIdx.x;
    if (p >= NPTS) return;
    u64 pk = g_packed[p];
    int bin = (int)(pk >> 53);
    int pos = g_base[bin] + atomicAdd(&g_cursor[bin], 1);
    g_tmp[pos] = pk;
}

// ---------------- per-bucket exact rank + emit (round 2 fuses anchor) -------
__global__ void k_bucket(int round, const float* __restrict__ zv,
                         const float* __restrict__ zi,
                         const long long* __restrict__ lab) {
    int w = (blockIdx.x * blockDim.x + threadIdx.x) >> 5;
    int lane = threadIdx.x & 31;
    if (w >= NBIN) return;
    int start = g_base[w], end = g_base[w + 1], m = end - start;
    if (round == 2 && start >= SANCH) {          // only first 5000 consumed
        if (lane == 0) g_hist[w] = 0;
        return;
    }
    for (int e = lane; e < m; e += 32) {
        u64 me = g_tmp[start + e];
        int r = 0;
        for (int f = 0; f < m; f++) r += (g_tmp[start + f] < me) ? 1 : 0;
        int v = (int)(me & 0xffffffffu);
        int slot = start + r;
        if (round == 1) {
            g_val1[slot] = v;
        } else if (slot < SANCH) {
            // fused anchor: idx = val2[slot]; pos logit, label, zv row copy
            int idx = g_val1[v];
            const float4* a4 = (const float4*)(zv + (size_t)idx * 64);
            const float4* b4 = (const float4*)(zi + (size_t)idx * 64);
            float4*       o4 = (float4*)(g_zvS + (size_t)slot * 64);
            float acc = 0.f;
#pragma unroll
            for (int q = 0; q < 16; q++) {
                float4 a = a4[q]; float4 b = b4[q];
                acc += a.x * b.x + a.y * b.y + a.z * b.z + a.w * b.w;
                o4[q] = a;
            }
            g_pos[slot]  = acc * INV_TEMP;
            g_labS[slot] = (int)lab[idx];
        }
    }
    if (lane == 0) g_hist[w] = 0;                // ready for next round / replay
}

// ---------------- main: lean sweep + post label filter + top-256 + InfoNCE --
__global__ __launch_bounds__(256, 6)
void k_main(const float* __restrict__ zimg, const long long* __restrict__ lab) {
    __shared__ u64 cands[CANDMAX];     // (v - TPRE)<<32 | j  (unfiltered)
    __shared__ u64 cands2[CANDMAX];    // label-filtered
    __shared__ int hist[256];
    __shared__ int sel[NNEG];
    __shared__ u64 eqb[64];
    __shared__ int s_cnt, s_cnt2, s_cgt, s_eq, s_b1, s_nd;
    __shared__ float zrow[64];
    __shared__ float red[8];
    __shared__ float s_m;

    const int s   = blockIdx.x;
    const int tid = threadIdx.x;
    const int lane = tid & 31;
    const int cls = g_labS[s];

    if (tid == 0) { s_cnt = 0; s_cnt2 = 0; s_cgt = 0; s_eq = 0; }
    sel[tid] = 0;
    hist[tid] = 0;
    if (tid < 64) zrow[tid] = g_zvS[s * 64 + tid];
    __syncthreads();

    // ---- sweep: 20000 threefry, prefilter bits >= TBITS (label-free) --------
    const uint32_t k0 = g_keys[0], k1 = g_keys[1];
    const uint32_t base = (uint32_t)s * 20000u;
    for (int j = tid; j < NPTS; j += 256) {
        uint32_t o0, o1;
        tf2x32(k0, k1, 0u, base + (uint32_t)j, o0, o1);
        uint32_t bits = o0 ^ o1;
        if (bits >= TBITS) {                 // == (bits>>9) >= TPRE
            uint32_t v = bits >> 9;
            int q = atomicAdd(&s_cnt, 1);
            if (q < CANDMAX)
                cands[q] = (((u64)(v - TPRE)) << 32) | (unsigned)j;
        }
    }
    __syncthreads();

    // ---- label filter: multiset identical to masked sweep -------------------
    int cnt = s_cnt; if (cnt > CANDMAX) cnt = CANDMAX;
    for (int t = tid; t < cnt; t += 256) {
        u64 cd = cands[t];
        int j = (int)(cd & 0xffffffffu);
        if ((int)lab[j] != cls) {
            int q = atomicAdd(&s_cnt2, 1);
            cands2[q] = cd;
        }
    }
    __syncthreads();
    int cnt2 = s_cnt2;

    // ---- level-1 histogram on top 8 of the 18 prefiltered bits --------------
    for (int t = tid; t < cnt2; t += 256) {
        uint32_t u = (uint32_t)(cands2[t] >> 32);
        atomicAdd(&hist[u >> 10], 1);
    }
    __syncthreads();
    if (tid == 0) {
        int need = NNEG, b;
        for (b = 255; b > 0; b--) { int h = hist[b]; if (h >= need) break; need -= h; }
        s_b1 = b; s_nd = need;
    }
    __syncthreads();
    const int b1 = s_b1;

    for (int t = tid; t < cnt2; t += 256) {
        u64 cd = cands2[t];
        int bin = (int)((uint32_t)(cd >> 32) >> 10);
        if (bin > b1) {
            int q = atomicAdd(&s_cgt, 1);
            if (q < NNEG) sel[q] = (int)(cd & 0xffffffffu);
        } else if (bin == b1) {
            int q = atomicAdd(&s_eq, 1);
            if (q < 64) eqb[q] = cd;
        }
    }
    __syncthreads();
    if (tid == 0) {
        // take nd best from boundary bin: max value first, ties -> lowest j
        int cg = s_cgt, nd = s_nd, ec = s_eq; if (ec > 64) ec = 64;
        for (int r = 0; r < nd && cg < NNEG; r++) {
            int bi = -1; uint32_t bu = 0; uint32_t bj = 0xffffffffu;
            for (int t = 0; t < ec; t++) {
                uint32_t u = (uint32_t)(eqb[t] >> 32);
                uint32_t j = (uint32_t)(eqb[t] & 0xffffffffu);
                if (j == 0x00ffffffu) continue;
                if (u > bu || (u == bu && j < bj)) { bu = u; bj = j; bi = t; }
            }
            if (bi < 0) break;
            sel[cg++] = (int)bj;
            eqb[bi] = 0x00ffffffull;
        }
    }
    __syncthreads();

    // ---- similarities for the 256 selected negatives -------------------------
    float x;
    {
        int j = sel[tid];
        const float4* zi4 = (const float4*)(zimg + (size_t)j * 64);
        const float4* zr4 = (const float4*)zrow;
        float acc = 0.f;
#pragma unroll
        for (int q = 0; q < 16; q++) {
            float4 a = zi4[q]; float4 b = zr4[q];
            acc += a.x * b.x + a.y * b.y + a.z * b.z + a.w * b.w;
        }
        x = acc * INV_TEMP;
    }
    const float pos = g_pos[s];

    float m = x;
#pragma unroll
    for (int off = 16; off; off >>= 1) m = fmaxf(m, __shfl_xor_sync(0xffffffffu, m, off));
    if (lane == 0) red[tid >> 5] = m;
    __syncthreads();
    if (tid == 0) {
        float mm = pos;
#pragma unroll
        for (int w = 0; w < 8; w++) mm = fmaxf(mm, red[w]);
        s_m = mm;
    }
    __syncthreads();
    m = s_m;

    float e = expf(x - m);
#pragma unroll
    for (int off = 16; off; off >>= 1) e += __shfl_xor_sync(0xffffffffu, e, off);
    if (lane == 0) red[tid >> 5] = e;
    __syncthreads();
    if (tid == 0) {
        float ssum = expf(pos - m);
#pragma unroll
        for (int w = 0; w < 8; w++) ssum += red[w];
        atomicAdd(&g_loss, (double)(logf(ssum) + m - pos));
    }
}

__global__ void k_final(float* out) {
    out[0] = (float)(0.1 * g_loss / 5000.0);
}

// ---------------- launch ----------------------------------------------------
extern "C" void kernel_launch(void* const* d_in, const int* in_sizes, int n_in,
                              void* d_out, int out_size) {
    const float*     zv  = (const float*)d_in[0];
    const float*     zi  = (const float*)d_in[1];
    const long long* lab = (const long long*)d_in[2];

    k_setup<<<(NBIN + 255) / 256, 256>>>();

    // permutation round 1 (sub1 = g_keys[2..3])
    k_hash_hist<<<(NPTS + 255) / 256, 256>>>(2);
    k_scan<<<1, 1024>>>();
    k_scatter<<<(NPTS + 255) / 256, 256>>>();
    k_bucket<<<NBIN / 8, 256>>>(1, zv, zi, lab);
    // permutation round 2 (sub2 = g_keys[4..5]) — bucket fuses anchor prep
    k_hash_hist<<<(NPTS + 255) / 256, 256>>>(4);
    k_scan<<<1, 1024>>>();
    k_scatter<<<(NPTS + 255) / 256, 256>>>();
    k_bucket<<<NBIN / 8, 256>>>(2, zv, zi, lab);

    k_main<<<SANCH, 256>>>(zi, lab);
    k_final<<<1, 1>>>((float*)d_out);
}